// round 11
// baseline (speedup 1.0000x reference)
#include <cuda_runtime.h>

#define HW 65536            // 256*256
#define IMGW 256
#define NWIN 32
#define SCALE 0.25f

typedef unsigned long long ull;

__device__ float g_qkv[2 * 288 * HW];
__device__ float g_att[2 * 96 * HW];

// ---------- f32x2 helpers ----------
__device__ __forceinline__ ull pack2(float a, float b) {
    ull r; asm("mov.b64 %0,{%1,%2};" : "=l"(r) : "f"(a), "f"(b)); return r;
}
__device__ __forceinline__ float2 unpack2(ull v) {
    float2 r; asm("mov.b64 {%0,%1},%2;" : "=f"(r.x), "=f"(r.y) : "l"(v)); return r;
}
__device__ __forceinline__ ull ffma2(ull a, ull b, ull c) {
    ull d; asm("fma.rn.f32x2 %0,%1,%2,%3;" : "=l"(d) : "l"(a), "l"(b), "l"(c)); return d;
}
__device__ __forceinline__ ull fadd2(ull a, ull b) {
    ull d; asm("add.rn.f32x2 %0,%1,%2;" : "=l"(d) : "l"(a), "l"(b)); return d;
}
__device__ __forceinline__ void lds2x64(ull& a, ull& b, unsigned addr) {
    asm("ld.shared.v2.u64 {%0,%1},[%2];" : "=l"(a), "=l"(b) : "r"(addr));
}

// ---------- tf32 helpers ----------
__device__ __forceinline__ float tf32_round(float x) {
    unsigned u; asm("cvt.rna.tf32.f32 %0, %1;" : "=r"(u) : "f"(x));
    return __uint_as_float(u);
}
__device__ __forceinline__ void mma_tf32(float& d0, float& d1, float& d2, float& d3,
                                         unsigned a0, unsigned a1, unsigned a2, unsigned a3,
                                         unsigned b0, unsigned b1) {
    asm("mma.sync.aligned.m16n8k8.row.col.f32.tf32.tf32.f32 "
        "{%0,%1,%2,%3},{%4,%5,%6,%7},{%8,%9},{%0,%1,%2,%3};"
        : "+f"(d0), "+f"(d1), "+f"(d2), "+f"(d3)
        : "r"(a0), "r"(a1), "r"(a2), "r"(a3), "r"(b0), "r"(b1));
}

// ---------------------------------------------------------------------------
// Pointwise GEMM via tensor cores (3xTF32) — unchanged from R10 (202us + ~67us).
// ---------------------------------------------------------------------------
template <int OC>
__global__ __launch_bounds__(256) void mma_gemm(
    const float* __restrict__ X, const float* __restrict__ W,
    const float* __restrict__ Bias, float* __restrict__ Y)
{
    __shared__ __align__(16) float XPhi[2][4][2][260];
    __shared__ __align__(16) float XPlo[2][4][2][260];
    __shared__ __align__(16) float WPhi[2][4][2][36];
    __shared__ __align__(16) float WPlo[2][4][2][36];

    const int b   = blockIdx.z;
    const int o0  = blockIdx.y * 32;
    const int p0  = blockIdx.x * 256;
    const int tid = threadIdx.x;
    const int warp = tid >> 5;
    const int lane = tid & 31;
    const int g = lane >> 2;
    const int t = lane & 3;
    const int om = (warp >> 2) * 16;
    const int nq = (warp & 3) * 64;

    float acc[8][4];
#pragma unroll
    for (int nb = 0; nb < 8; nb++)
#pragma unroll
        for (int r = 0; r < 4; r++) acc[nb][r] = 0.f;

    for (int kc = 0; kc < 96; kc += 16) {
        __syncthreads();
#pragma unroll
        for (int pss = 0; pss < 4; pss++) {
            int j  = tid + pss * 256;
            int k  = j >> 6;
            int n4 = j & 63;
            float4 xv = *(const float4*)(X + (size_t)(b * 96 + kc + k) * HW + p0 + n4 * 4);
            int s  = k >> 3;
            int kk = k & 7;
            int tt = kk & 3;
            int comp = kk >> 2;
            float4 hi4, lo4;
            hi4.x = tf32_round(xv.x);  lo4.x = tf32_round(xv.x - hi4.x);
            hi4.y = tf32_round(xv.y);  lo4.y = tf32_round(xv.y - hi4.y);
            hi4.z = tf32_round(xv.z);  lo4.z = tf32_round(xv.z - hi4.z);
            hi4.w = tf32_round(xv.w);  lo4.w = tf32_round(xv.w - hi4.w);
            *(float4*)&XPhi[s][tt][comp][n4 * 4] = hi4;
            *(float4*)&XPlo[s][tt][comp][n4 * 4] = lo4;
        }
#pragma unroll
        for (int pss = 0; pss < 2; pss++) {
            int i = tid + pss * 256;
            int o = i & 31;
            int k = i >> 5;
            float v  = W[(o0 + o) * 96 + kc + k];
            float hi = tf32_round(v);
            float lo = tf32_round(v - hi);
            int s  = k >> 3;
            int kk = k & 7;
            int tt = kk & 3;
            int comp = kk >> 2;
            WPhi[s][tt][comp][o] = hi;
            WPlo[s][tt][comp][o] = lo;
        }
        __syncthreads();

#pragma unroll
        for (int s = 0; s < 2; s++) {
            unsigned Ah0 = __float_as_uint(WPhi[s][t][0][om + g]);
            unsigned Ah1 = __float_as_uint(WPhi[s][t][0][om + g + 8]);
            unsigned Ah2 = __float_as_uint(WPhi[s][t][1][om + g]);
            unsigned Ah3 = __float_as_uint(WPhi[s][t][1][om + g + 8]);
            unsigned Al0 = __float_as_uint(WPlo[s][t][0][om + g]);
            unsigned Al1 = __float_as_uint(WPlo[s][t][0][om + g + 8]);
            unsigned Al2 = __float_as_uint(WPlo[s][t][1][om + g]);
            unsigned Al3 = __float_as_uint(WPlo[s][t][1][om + g + 8]);

#pragma unroll
            for (int nb = 0; nb < 8; nb++) {
                int n = nq + nb * 8 + g;
                unsigned Bh0 = __float_as_uint(XPhi[s][t][0][n]);
                unsigned Bh1 = __float_as_uint(XPhi[s][t][1][n]);
                unsigned Bl0 = __float_as_uint(XPlo[s][t][0][n]);
                unsigned Bl1 = __float_as_uint(XPlo[s][t][1][n]);
                mma_tf32(acc[nb][0], acc[nb][1], acc[nb][2], acc[nb][3],
                         Ah0, Ah1, Ah2, Ah3, Bh0, Bh1);
                mma_tf32(acc[nb][0], acc[nb][1], acc[nb][2], acc[nb][3],
                         Ah0, Ah1, Ah2, Ah3, Bl0, Bl1);
                mma_tf32(acc[nb][0], acc[nb][1], acc[nb][2], acc[nb][3],
                         Al0, Al1, Al2, Al3, Bh0, Bh1);
            }
        }
    }

    const int r0 = o0 + om + g;
    const int r1 = r0 + 8;
    const float bias0 = Bias[r0];
    const float bias1 = Bias[r1];
    float* y0 = Y + (size_t)(b * OC + r0) * HW + p0 + nq + t * 2;
    float* y1 = Y + (size_t)(b * OC + r1) * HW + p0 + nq + t * 2;
#pragma unroll
    for (int nb = 0; nb < 8; nb++) {
        *(float2*)(y0 + nb * 8) = make_float2(acc[nb][0] + bias0, acc[nb][1] + bias0);
        *(float2*)(y1 + nb * 8) = make_float2(acc[nb][2] + bias1, acc[nb][3] + bias1);
    }
}

// ---------------------------------------------------------------------------
// Window attention v3: per key-row ki, three batched phases:
//   (1) 12 independent logit chains  (2) 12 batched exps + split denominators
//   (3) 12 batched AV accumulations.
// Breaks the per-key serial LDS->dot->exp->AV critical path of v1/v2.
// ---------------------------------------------------------------------------
__global__ __launch_bounds__(128, 4) void attn_kernel(
    const float* __restrict__ rel_h, const float* __restrict__ rel_w)
{
    __shared__ __align__(16) float ksm[2 * 144 * 20];
    __shared__ __align__(16) float vsm[2 * 144 * 20];
    __shared__ __align__(16) float rhs_[23 * 16];
    __shared__ __align__(16) float rws_[23 * 16];

    const int hp  = blockIdx.x % 3;
    const int win = blockIdx.x / 3;
    const int b   = win >> 10;
    const int wy  = (win >> 5) & 31;
    const int wx  = win & 31;
    const int tid = threadIdx.x;
    const int h0  = hp * 2;

    for (int i = tid; i < 23 * 16; i += 128) {
        rhs_[i] = rel_h[i];
        rws_[i] = rel_w[i];
    }

    const int y0 = wy * 8 - 2, x0 = wx * 8 - 2;
    for (int i = tid; i < 2 * 16 * 144; i += 128) {
        int j  = i % 12;
        int tt = i / 12;
        int ii = tt % 12;  tt /= 12;
        int d  = tt & 15;
        int hh = tt >> 4;
        int gy = y0 + ii, gx = x0 + j;
        float kv = 0.f, vv = 0.f;
        if ((unsigned)gy < 256u && (unsigned)gx < 256u) {
            const float* p = g_qkv +
                ((size_t)b * 288 + 96 + (h0 + hh) * 16 + d) * HW + gy * IMGW + gx;
            kv = p[0];
            vv = p[(size_t)96 * HW];
        }
        int si = (hh * 144 + ii * 12 + j) * 20 + d;
        ksm[si] = kv;
        vsm[si] = vv;
    }
    __syncthreads();

    const int hh   = tid >> 6;
    const int head = h0 + hh;
    const int qi   = tid & 63;
    const int x    = qi >> 3, y = qi & 7;
    const int gy   = wy * 8 + x, gx = wx * 8 + y;

    ull qp[8];
    {
        const float* qb = g_qkv + ((size_t)b * 288 + head * 16) * HW + gy * IMGW + gx;
#pragma unroll
        for (int d = 0; d < 8; d++) {
            float a = SCALE * qb[(size_t)(2 * d) * HW];
            float c = SCALE * qb[(size_t)(2 * d + 1) * HW];
            qp[d] = pack2(a, c);
        }
    }

    float Bv[12];
#pragma unroll
    for (int kj = 0; kj < 12; kj++) {
        const ull* rw = (const ull*)&rws_[(kj - y + 11) * 16];
        ull s0 = 0, s1 = 0;
#pragma unroll
        for (int d = 0; d < 8; d += 2) {
            s0 = ffma2(qp[d],     rw[d],     s0);
            s1 = ffma2(qp[d + 1], rw[d + 1], s1);
        }
        float2 f = unpack2(fadd2(s0, s1));
        Bv[kj] = f.x + f.y;
    }

    float sden0 = 0.f, sden1 = 0.f, sden2 = 0.f, sden3 = 0.f;
    ull acc[8] = {};
    const unsigned kaddr = (unsigned)__cvta_generic_to_shared(&ksm[hh * 144 * 20]);
    const unsigned vaddr = (unsigned)__cvta_generic_to_shared(&vsm[hh * 144 * 20]);

    for (int ki = 0; ki < 12; ki++) {
        float aki;
        {
            const ull* rh = (const ull*)&rhs_[(ki - x + 11) * 16];
            ull s0 = 0, s1 = 0;
#pragma unroll
            for (int d = 0; d < 8; d += 2) {
                s0 = ffma2(qp[d],     rh[d],     s0);
                s1 = ffma2(qp[d + 1], rh[d + 1], s1);
            }
            float2 f = unpack2(fadd2(s0, s1));
            aki = f.x + f.y;
        }

        const unsigned kro = kaddr + ki * 12 * 80;
        const unsigned vro = vaddr + ki * 12 * 80;

        // --- phase 1: 12 independent logit chains ---
        float l[12];
#pragma unroll
        for (int kj = 0; kj < 12; kj++) {
            ull k0, k1, k2, k3, k4, k5, k6, k7;
            lds2x64(k0, k1, kro + kj * 80);
            lds2x64(k2, k3, kro + kj * 80 + 16);
            lds2x64(k4, k5, kro + kj * 80 + 32);
            lds2x64(k6, k7, kro + kj * 80 + 48);
            ull la = pack2(aki, Bv[kj]);
            la = ffma2(qp[0], k0, la);
            la = ffma2(qp[1], k1, la);
            la = ffma2(qp[2], k2, la);
            la = ffma2(qp[3], k3, la);
            la = ffma2(qp[4], k4, la);
            la = ffma2(qp[5], k5, la);
            la = ffma2(qp[6], k6, la);
            la = ffma2(qp[7], k7, la);
            float2 lf = unpack2(la);
            l[kj] = lf.x + lf.y;
        }

        // --- phase 2: batched exps + split denominator partials ---
        float p[12];
#pragma unroll
        for (int kj = 0; kj < 12; kj++)
            p[kj] = __expf(l[kj]);
        sden0 += p[0] + p[4];
        sden1 += p[1] + p[5];
        sden2 += p[2] + p[6];
        sden3 += p[3] + p[7];
        sden0 += p[8];
        sden1 += p[9];
        sden2 += p[10];
        sden3 += p[11];

        // --- phase 3: batched AV accumulation ---
#pragma unroll
        for (int kj = 0; kj < 12; kj++) {
            ull pd = pack2(p[kj], p[kj]);
            ull v0, v1, v2, v3, v4, v5, v6, v7;
            lds2x64(v0, v1, vro + kj * 80);
            lds2x64(v2, v3, vro + kj * 80 + 16);
            lds2x64(v4, v5, vro + kj * 80 + 32);
            lds2x64(v6, v7, vro + kj * 80 + 48);
            acc[0] = ffma2(pd, v0, acc[0]);
            acc[1] = ffma2(pd, v1, acc[1]);
            acc[2] = ffma2(pd, v2, acc[2]);
            acc[3] = ffma2(pd, v3, acc[3]);
            acc[4] = ffma2(pd, v4, acc[4]);
            acc[5] = ffma2(pd, v5, acc[5]);
            acc[6] = ffma2(pd, v6, acc[6]);
            acc[7] = ffma2(pd, v7, acc[7]);
        }
    }

    float inv = 1.f / ((sden0 + sden1) + (sden2 + sden3));
    float* outp = g_att + ((size_t)b * 96 + head * 16) * HW + gy * IMGW + gx;
#pragma unroll
    for (int j = 0; j < 8; j++) {
        float2 f = unpack2(acc[j]);
        outp[(size_t)(2 * j) * HW]     = f.x * inv;
        outp[(size_t)(2 * j + 1) * HW] = f.y * inv;
    }
}

// ---------------------------------------------------------------------------
extern "C" void kernel_launch(void* const* d_in, const int* in_sizes, int n_in,
                              void* d_out, int out_size)
{
    (void)in_sizes; (void)n_in; (void)out_size;
    const float* x      = (const float*)d_in[0];
    const float* qkv_w  = (const float*)d_in[1];
    const float* qkv_b  = (const float*)d_in[2];
    const float* proj_w = (const float*)d_in[3];
    const float* proj_b = (const float*)d_in[4];
    const float* rel_h  = (const float*)d_in[5];
    const float* rel_w  = (const float*)d_in[6];
    float* out = (float*)d_out;

    float* qkv_ptr = nullptr;
    float* att_ptr = nullptr;
    cudaGetSymbolAddress((void**)&qkv_ptr, g_qkv);
    cudaGetSymbolAddress((void**)&att_ptr, g_att);

    // 1) QKV pointwise GEMM (tensor cores, 3xTF32): (2,96,HW) -> (2,288,HW)
    mma_gemm<288><<<dim3(HW / 256, 288 / 32, 2), 256>>>(x, qkv_w, qkv_b, qkv_ptr);

    // 2) Windowed halo attention with rel-pos + softmax -> (2,96,HW)
    attn_kernel<<<2 * NWIN * NWIN * 3, 128>>>(rel_h, rel_w);

    // 3) Output projection (tensor cores): (2,96,HW) -> (2,96,HW)
    mma_gemm<96><<<dim3(HW / 256, 96 / 32, 2), 256>>>(att_ptr, proj_w, proj_b, out);
}

// round 13
// speedup vs baseline: 1.0093x; 1.0093x over previous
#include <cuda_runtime.h>

#define HW 65536            // 256*256
#define IMGW 256
#define NWIN 32
#define SCALE 0.25f

typedef unsigned long long ull;

__device__ float g_qkv[2 * 288 * HW];
__device__ float g_att[2 * 96 * HW];

// ---------- f32x2 helpers ----------
__device__ __forceinline__ ull pack2(float a, float b) {
    ull r; asm("mov.b64 %0,{%1,%2};" : "=l"(r) : "f"(a), "f"(b)); return r;
}
__device__ __forceinline__ float2 unpack2(ull v) {
    float2 r; asm("mov.b64 {%0,%1},%2;" : "=f"(r.x), "=f"(r.y) : "l"(v)); return r;
}
__device__ __forceinline__ ull ffma2(ull a, ull b, ull c) {
    ull d; asm("fma.rn.f32x2 %0,%1,%2,%3;" : "=l"(d) : "l"(a), "l"(b), "l"(c)); return d;
}
__device__ __forceinline__ ull fadd2(ull a, ull b) {
    ull d; asm("add.rn.f32x2 %0,%1,%2;" : "=l"(d) : "l"(a), "l"(b)); return d;
}
__device__ __forceinline__ void lds2x64(ull& a, ull& b, unsigned addr) {
    asm("ld.shared.v2.u64 {%0,%1},[%2];" : "=l"(a), "=l"(b) : "r"(addr));
}

// ---------- tf32 helpers ----------
__device__ __forceinline__ float tf32_round(float x) {
    unsigned u; asm("cvt.rna.tf32.f32 %0, %1;" : "=r"(u) : "f"(x));
    return __uint_as_float(u);
}
__device__ __forceinline__ void mma_tf32(float& d0, float& d1, float& d2, float& d3,
                                         unsigned a0, unsigned a1, unsigned a2, unsigned a3,
                                         unsigned b0, unsigned b1) {
    asm("mma.sync.aligned.m16n8k8.row.col.f32.tf32.tf32.f32 "
        "{%0,%1,%2,%3},{%4,%5,%6,%7},{%8,%9},{%0,%1,%2,%3};"
        : "+f"(d0), "+f"(d1), "+f"(d2), "+f"(d3)
        : "r"(a0), "r"(a1), "r"(a2), "r"(a3), "r"(b0), "r"(b1));
}

// ---------------------------------------------------------------------------
// Pointwise GEMM via tensor cores, 2-pass tf32 split:
//   Y ≈ Wh·Xh + Wh·Xl     (W-lo term dropped: ~2.8e-4 RMS rel err, budget 1e-3)
// Removes the WPlo path entirely; regs drop -> 4 blocks/SM.
// ---------------------------------------------------------------------------
template <int OC>
__global__ __launch_bounds__(256, 4) void mma_gemm(
    const float* __restrict__ X, const float* __restrict__ W,
    const float* __restrict__ Bias, float* __restrict__ Y)
{
    __shared__ __align__(16) float XPhi[2][4][2][260];
    __shared__ __align__(16) float XPlo[2][4][2][260];
    __shared__ __align__(16) float WPhi[2][4][2][36];

    const int b   = blockIdx.z;
    const int o0  = blockIdx.y * 32;
    const int p0  = blockIdx.x * 256;
    const int tid = threadIdx.x;
    const int warp = tid >> 5;
    const int lane = tid & 31;
    const int g = lane >> 2;
    const int t = lane & 3;
    const int om = (warp >> 2) * 16;
    const int nq = (warp & 3) * 64;

    float acc[8][4];
#pragma unroll
    for (int nb = 0; nb < 8; nb++)
#pragma unroll
        for (int r = 0; r < 4; r++) acc[nb][r] = 0.f;

    for (int kc = 0; kc < 96; kc += 16) {
        __syncthreads();
        // ---- stage X chunk [16][256]: hi/lo split, vectorized stores ----
#pragma unroll
        for (int pss = 0; pss < 4; pss++) {
            int j  = tid + pss * 256;
            int k  = j >> 6;
            int n4 = j & 63;
            float4 xv = *(const float4*)(X + (size_t)(b * 96 + kc + k) * HW + p0 + n4 * 4);
            int s  = k >> 3;
            int kk = k & 7;
            int tt = kk & 3;
            int comp = kk >> 2;
            float4 hi4, lo4;
            hi4.x = tf32_round(xv.x);  lo4.x = tf32_round(xv.x - hi4.x);
            hi4.y = tf32_round(xv.y);  lo4.y = tf32_round(xv.y - hi4.y);
            hi4.z = tf32_round(xv.z);  lo4.z = tf32_round(xv.z - hi4.z);
            hi4.w = tf32_round(xv.w);  lo4.w = tf32_round(xv.w - hi4.w);
            *(float4*)&XPhi[s][tt][comp][n4 * 4] = hi4;
            *(float4*)&XPlo[s][tt][comp][n4 * 4] = lo4;
        }
        // ---- stage W chunk [16][32] (hi only) ----
#pragma unroll
        for (int pss = 0; pss < 2; pss++) {
            int i = tid + pss * 256;
            int o = i & 31;
            int k = i >> 5;
            float v  = W[(o0 + o) * 96 + kc + k];
            int s  = k >> 3;
            int kk = k & 7;
            int tt = kk & 3;
            int comp = kk >> 2;
            WPhi[s][tt][comp][o] = tf32_round(v);
        }
        __syncthreads();

#pragma unroll
        for (int s = 0; s < 2; s++) {
            unsigned Ah0 = __float_as_uint(WPhi[s][t][0][om + g]);
            unsigned Ah1 = __float_as_uint(WPhi[s][t][0][om + g + 8]);
            unsigned Ah2 = __float_as_uint(WPhi[s][t][1][om + g]);
            unsigned Ah3 = __float_as_uint(WPhi[s][t][1][om + g + 8]);

#pragma unroll
            for (int nb = 0; nb < 8; nb++) {
                int n = nq + nb * 8 + g;
                unsigned Bh0 = __float_as_uint(XPhi[s][t][0][n]);
                unsigned Bh1 = __float_as_uint(XPhi[s][t][1][n]);
                unsigned Bl0 = __float_as_uint(XPlo[s][t][0][n]);
                unsigned Bl1 = __float_as_uint(XPlo[s][t][1][n]);
                mma_tf32(acc[nb][0], acc[nb][1], acc[nb][2], acc[nb][3],
                         Ah0, Ah1, Ah2, Ah3, Bh0, Bh1);
                mma_tf32(acc[nb][0], acc[nb][1], acc[nb][2], acc[nb][3],
                         Ah0, Ah1, Ah2, Ah3, Bl0, Bl1);
            }
        }
    }

    const int r0 = o0 + om + g;
    const int r1 = r0 + 8;
    const float bias0 = Bias[r0];
    const float bias1 = Bias[r1];
    float* y0 = Y + (size_t)(b * OC + r0) * HW + p0 + nq + t * 2;
    float* y1 = Y + (size_t)(b * OC + r1) * HW + p0 + nq + t * 2;
#pragma unroll
    for (int nb = 0; nb < 8; nb++) {
        *(float2*)(y0 + nb * 8) = make_float2(acc[nb][0] + bias0, acc[nb][1] + bias0);
        *(float2*)(y1 + nb * 8) = make_float2(acc[nb][2] + bias1, acc[nb][3] + bias1);
    }
}

// ---------------------------------------------------------------------------
// Window attention — R11 version (throughput-bound at ~339us; unchanged).
// ---------------------------------------------------------------------------
__global__ __launch_bounds__(128, 4) void attn_kernel(
    const float* __restrict__ rel_h, const float* __restrict__ rel_w)
{
    __shared__ __align__(16) float ksm[2 * 144 * 20];
    __shared__ __align__(16) float vsm[2 * 144 * 20];
    __shared__ __align__(16) float rhs_[23 * 16];
    __shared__ __align__(16) float rws_[23 * 16];

    const int hp  = blockIdx.x % 3;
    const int win = blockIdx.x / 3;
    const int b   = win >> 10;
    const int wy  = (win >> 5) & 31;
    const int wx  = win & 31;
    const int tid = threadIdx.x;
    const int h0  = hp * 2;

    for (int i = tid; i < 23 * 16; i += 128) {
        rhs_[i] = rel_h[i];
        rws_[i] = rel_w[i];
    }

    const int y0 = wy * 8 - 2, x0 = wx * 8 - 2;
    for (int i = tid; i < 2 * 16 * 144; i += 128) {
        int j  = i % 12;
        int tt = i / 12;
        int ii = tt % 12;  tt /= 12;
        int d  = tt & 15;
        int hh = tt >> 4;
        int gy = y0 + ii, gx = x0 + j;
        float kv = 0.f, vv = 0.f;
        if ((unsigned)gy < 256u && (unsigned)gx < 256u) {
            const float* p = g_qkv +
                ((size_t)b * 288 + 96 + (h0 + hh) * 16 + d) * HW + gy * IMGW + gx;
            kv = p[0];
            vv = p[(size_t)96 * HW];
        }
        int si = (hh * 144 + ii * 12 + j) * 20 + d;
        ksm[si] = kv;
        vsm[si] = vv;
    }
    __syncthreads();

    const int hh   = tid >> 6;
    const int head = h0 + hh;
    const int qi   = tid & 63;
    const int x    = qi >> 3, y = qi & 7;
    const int gy   = wy * 8 + x, gx = wx * 8 + y;

    ull qp[8];
    {
        const float* qb = g_qkv + ((size_t)b * 288 + head * 16) * HW + gy * IMGW + gx;
#pragma unroll
        for (int d = 0; d < 8; d++) {
            float a = SCALE * qb[(size_t)(2 * d) * HW];
            float c = SCALE * qb[(size_t)(2 * d + 1) * HW];
            qp[d] = pack2(a, c);
        }
    }

    float Bv[12];
#pragma unroll
    for (int kj = 0; kj < 12; kj++) {
        const ull* rw = (const ull*)&rws_[(kj - y + 11) * 16];
        ull s0 = 0, s1 = 0;
#pragma unroll
        for (int d = 0; d < 8; d += 2) {
            s0 = ffma2(qp[d],     rw[d],     s0);
            s1 = ffma2(qp[d + 1], rw[d + 1], s1);
        }
        float2 f = unpack2(fadd2(s0, s1));
        Bv[kj] = f.x + f.y;
    }

    float sden0 = 0.f, sden1 = 0.f, sden2 = 0.f, sden3 = 0.f;
    ull acc[8] = {};
    const unsigned kaddr = (unsigned)__cvta_generic_to_shared(&ksm[hh * 144 * 20]);
    const unsigned vaddr = (unsigned)__cvta_generic_to_shared(&vsm[hh * 144 * 20]);

    for (int ki = 0; ki < 12; ki++) {
        float aki;
        {
            const ull* rh = (const ull*)&rhs_[(ki - x + 11) * 16];
            ull s0 = 0, s1 = 0;
#pragma unroll
            for (int d = 0; d < 8; d += 2) {
                s0 = ffma2(qp[d],     rh[d],     s0);
                s1 = ffma2(qp[d + 1], rh[d + 1], s1);
            }
            float2 f = unpack2(fadd2(s0, s1));
            aki = f.x + f.y;
        }

        const unsigned kro = kaddr + ki * 12 * 80;
        const unsigned vro = vaddr + ki * 12 * 80;

        float l[12];
#pragma unroll
        for (int kj = 0; kj < 12; kj++) {
            ull k0, k1, k2, k3, k4, k5, k6, k7;
            lds2x64(k0, k1, kro + kj * 80);
            lds2x64(k2, k3, kro + kj * 80 + 16);
            lds2x64(k4, k5, kro + kj * 80 + 32);
            lds2x64(k6, k7, kro + kj * 80 + 48);
            ull la = pack2(aki, Bv[kj]);
            la = ffma2(qp[0], k0, la);
            la = ffma2(qp[1], k1, la);
            la = ffma2(qp[2], k2, la);
            la = ffma2(qp[3], k3, la);
            la = ffma2(qp[4], k4, la);
            la = ffma2(qp[5], k5, la);
            la = ffma2(qp[6], k6, la);
            la = ffma2(qp[7], k7, la);
            float2 lf = unpack2(la);
            l[kj] = lf.x + lf.y;
        }

        float p[12];
#pragma unroll
        for (int kj = 0; kj < 12; kj++)
            p[kj] = __expf(l[kj]);
        sden0 += p[0] + p[4];
        sden1 += p[1] + p[5];
        sden2 += p[2] + p[6];
        sden3 += p[3] + p[7];
        sden0 += p[8];
        sden1 += p[9];
        sden2 += p[10];
        sden3 += p[11];

#pragma unroll
        for (int kj = 0; kj < 12; kj++) {
            ull pd = pack2(p[kj], p[kj]);
            ull v0, v1, v2, v3, v4, v5, v6, v7;
            lds2x64(v0, v1, vro + kj * 80);
            lds2x64(v2, v3, vro + kj * 80 + 16);
            lds2x64(v4, v5, vro + kj * 80 + 32);
            lds2x64(v6, v7, vro + kj * 80 + 48);
            acc[0] = ffma2(pd, v0, acc[0]);
            acc[1] = ffma2(pd, v1, acc[1]);
            acc[2] = ffma2(pd, v2, acc[2]);
            acc[3] = ffma2(pd, v3, acc[3]);
            acc[4] = ffma2(pd, v4, acc[4]);
            acc[5] = ffma2(pd, v5, acc[5]);
            acc[6] = ffma2(pd, v6, acc[6]);
            acc[7] = ffma2(pd, v7, acc[7]);
        }
    }

    float inv = 1.f / ((sden0 + sden1) + (sden2 + sden3));
    float* outp = g_att + ((size_t)b * 96 + head * 16) * HW + gy * IMGW + gx;
#pragma unroll
    for (int j = 0; j < 8; j++) {
        float2 f = unpack2(acc[j]);
        outp[(size_t)(2 * j) * HW]     = f.x * inv;
        outp[(size_t)(2 * j + 1) * HW] = f.y * inv;
    }
}

// ---------------------------------------------------------------------------
extern "C" void kernel_launch(void* const* d_in, const int* in_sizes, int n_in,
                              void* d_out, int out_size)
{
    (void)in_sizes; (void)n_in; (void)out_size;
    const float* x      = (const float*)d_in[0];
    const float* qkv_w  = (const float*)d_in[1];
    const float* qkv_b  = (const float*)d_in[2];
    const float* proj_w = (const float*)d_in[3];
    const float* proj_b = (const float*)d_in[4];
    const float* rel_h  = (const float*)d_in[5];
    const float* rel_w  = (const float*)d_in[6];
    float* out = (float*)d_out;

    float* qkv_ptr = nullptr;
    float* att_ptr = nullptr;
    cudaGetSymbolAddress((void**)&qkv_ptr, g_qkv);
    cudaGetSymbolAddress((void**)&att_ptr, g_att);

    // 1) QKV pointwise GEMM (tensor cores, 2-pass tf32): (2,96,HW) -> (2,288,HW)
    mma_gemm<288><<<dim3(HW / 256, 288 / 32, 2), 256>>>(x, qkv_w, qkv_b, qkv_ptr);

    // 2) Windowed halo attention with rel-pos + softmax -> (2,96,HW)
    attn_kernel<<<2 * NWIN * NWIN * 3, 128>>>(rel_h, rel_w);

    // 3) Output projection (tensor cores, 2-pass tf32): (2,96,HW) -> (2,96,HW)
    mma_gemm<96><<<dim3(HW / 256, 96 / 32, 2), 256>>>(att_ptr, proj_w, proj_b, out);
}

// round 14
// speedup vs baseline: 1.0535x; 1.0437x over previous
#include <cuda_runtime.h>

#define HW 65536            // 256*256
#define IMGW 256
#define NWIN 32
#define SCALE 0.25f

typedef unsigned long long ull;

__device__ float g_qkv[2 * 288 * HW];
__device__ float g_att[2 * 96 * HW];

// ---------- f32x2 helpers ----------
__device__ __forceinline__ ull pack2(float a, float b) {
    ull r; asm("mov.b64 %0,{%1,%2};" : "=l"(r) : "f"(a), "f"(b)); return r;
}
__device__ __forceinline__ float2 unpack2(ull v) {
    float2 r; asm("mov.b64 {%0,%1},%2;" : "=f"(r.x), "=f"(r.y) : "l"(v)); return r;
}
__device__ __forceinline__ ull ffma2(ull a, ull b, ull c) {
    ull d; asm("fma.rn.f32x2 %0,%1,%2,%3;" : "=l"(d) : "l"(a), "l"(b), "l"(c)); return d;
}
__device__ __forceinline__ ull fadd2(ull a, ull b) {
    ull d; asm("add.rn.f32x2 %0,%1,%2;" : "=l"(d) : "l"(a), "l"(b)); return d;
}
__device__ __forceinline__ void lds2x64(ull& a, ull& b, unsigned addr) {
    asm("ld.shared.v2.u64 {%0,%1},[%2];" : "=l"(a), "=l"(b) : "r"(addr));
}

// ---------- tf32 helpers ----------
__device__ __forceinline__ float tf32_round(float x) {
    unsigned u; asm("cvt.rna.tf32.f32 %0, %1;" : "=r"(u) : "f"(x));
    return __uint_as_float(u);
}
__device__ __forceinline__ void mma_tf32(float& d0, float& d1, float& d2, float& d3,
                                         unsigned a0, unsigned a1, unsigned a2, unsigned a3,
                                         unsigned b0, unsigned b1) {
    asm("mma.sync.aligned.m16n8k8.row.col.f32.tf32.tf32.f32 "
        "{%0,%1,%2,%3},{%4,%5,%6,%7},{%8,%9},{%0,%1,%2,%3};"
        : "+f"(d0), "+f"(d1), "+f"(d2), "+f"(d3)
        : "r"(a0), "r"(a1), "r"(a2), "r"(a3), "r"(b0), "r"(b1));
}

// ---------------------------------------------------------------------------
// Pointwise GEMM, 2-pass tf32 (Y ≈ Wh·Xh + Wh·Xl), v3:
//  - W staged ONCE for all 6 k-chunks (hoisted out of mainloop)
//  - X register double-buffer: next chunk's LDGs issued before compute,
//    hiding gmem latency behind the mma+LDS phase.
// ---------------------------------------------------------------------------
template <int OC>
__global__ __launch_bounds__(256, 3) void mma_gemm(
    const float* __restrict__ X, const float* __restrict__ W,
    const float* __restrict__ Bias, float* __restrict__ Y)
{
    __shared__ __align__(16) float XPhi[2][4][2][260];
    __shared__ __align__(16) float XPlo[2][4][2][260];
    __shared__ __align__(16) float WPhi[12][4][2][36];   // all 96 k, hi only

    const int b   = blockIdx.z;
    const int o0  = blockIdx.y * 32;
    const int p0  = blockIdx.x * 256;
    const int tid = threadIdx.x;
    const int warp = tid >> 5;
    const int lane = tid & 31;
    const int g = lane >> 2;
    const int t = lane & 3;
    const int om = (warp >> 2) * 16;
    const int nq = (warp & 3) * 64;

    // ---- stage ALL of W once: 32 outs x 96 k ----
    for (int i = tid; i < 32 * 96; i += 256) {
        int o = i & 31;
        int k = i >> 5;                       // 0..95
        WPhi[k >> 3][k & 3][(k >> 2) & 1][o] = tf32_round(W[(o0 + o) * 96 + k]);
    }

    float acc[8][4];
#pragma unroll
    for (int nb = 0; nb < 8; nb++)
#pragma unroll
        for (int r = 0; r < 4; r++) acc[nb][r] = 0.f;

    // ---- prologue: prefetch chunk 0 into registers ----
    float4 xv[4];
#pragma unroll
    for (int pss = 0; pss < 4; pss++) {
        int j  = tid + pss * 256;
        int k  = j >> 6;
        int n4 = j & 63;
        xv[pss] = *(const float4*)(X + (size_t)(b * 96 + k) * HW + p0 + n4 * 4);
    }

    for (int kc = 0; kc < 96; kc += 16) {
        __syncthreads();     // prior compute done (also orders W staging on iter 0)
        // ---- store prefetched X chunk to smem (hi/lo split) ----
#pragma unroll
        for (int pss = 0; pss < 4; pss++) {
            int j  = tid + pss * 256;
            int k  = j >> 6;
            int n4 = j & 63;
            int s  = k >> 3;
            int tt = k & 3;
            int comp = (k >> 2) & 1;
            float4 v = xv[pss];
            float4 hi4, lo4;
            hi4.x = tf32_round(v.x);  lo4.x = tf32_round(v.x - hi4.x);
            hi4.y = tf32_round(v.y);  lo4.y = tf32_round(v.y - hi4.y);
            hi4.z = tf32_round(v.z);  lo4.z = tf32_round(v.z - hi4.z);
            hi4.w = tf32_round(v.w);  lo4.w = tf32_round(v.w - hi4.w);
            *(float4*)&XPhi[s][tt][comp][n4 * 4] = hi4;
            *(float4*)&XPlo[s][tt][comp][n4 * 4] = lo4;
        }
        __syncthreads();

        // ---- prefetch NEXT chunk (latency hidden behind compute below) ----
        if (kc < 80) {
#pragma unroll
            for (int pss = 0; pss < 4; pss++) {
                int j  = tid + pss * 256;
                int k  = j >> 6;
                int n4 = j & 63;
                xv[pss] = *(const float4*)(X + (size_t)(b * 96 + kc + 16 + k) * HW + p0 + n4 * 4);
            }
        }

        // ---- compute on staged chunk ----
#pragma unroll
        for (int s = 0; s < 2; s++) {
            const int sg = (kc >> 3) + s;
            unsigned Ah0 = __float_as_uint(WPhi[sg][t][0][om + g]);
            unsigned Ah1 = __float_as_uint(WPhi[sg][t][0][om + g + 8]);
            unsigned Ah2 = __float_as_uint(WPhi[sg][t][1][om + g]);
            unsigned Ah3 = __float_as_uint(WPhi[sg][t][1][om + g + 8]);

#pragma unroll
            for (int nb = 0; nb < 8; nb++) {
                int n = nq + nb * 8 + g;
                unsigned Bh0 = __float_as_uint(XPhi[s][t][0][n]);
                unsigned Bh1 = __float_as_uint(XPhi[s][t][1][n]);
                unsigned Bl0 = __float_as_uint(XPlo[s][t][0][n]);
                unsigned Bl1 = __float_as_uint(XPlo[s][t][1][n]);
                mma_tf32(acc[nb][0], acc[nb][1], acc[nb][2], acc[nb][3],
                         Ah0, Ah1, Ah2, Ah3, Bh0, Bh1);
                mma_tf32(acc[nb][0], acc[nb][1], acc[nb][2], acc[nb][3],
                         Ah0, Ah1, Ah2, Ah3, Bl0, Bl1);
            }
        }
    }

    const int r0 = o0 + om + g;
    const int r1 = r0 + 8;
    const float bias0 = Bias[r0];
    const float bias1 = Bias[r1];
    float* y0 = Y + (size_t)(b * OC + r0) * HW + p0 + nq + t * 2;
    float* y1 = Y + (size_t)(b * OC + r1) * HW + p0 + nq + t * 2;
#pragma unroll
    for (int nb = 0; nb < 8; nb++) {
        *(float2*)(y0 + nb * 8) = make_float2(acc[nb][0] + bias0, acc[nb][1] + bias0);
        *(float2*)(y1 + nb * 8) = make_float2(acc[nb][2] + bias1, acc[nb][3] + bias1);
    }
}

// ---------------------------------------------------------------------------
// Window attention — unchanged (throughput-bound at ~339us).
// ---------------------------------------------------------------------------
__global__ __launch_bounds__(128, 4) void attn_kernel(
    const float* __restrict__ rel_h, const float* __restrict__ rel_w)
{
    __shared__ __align__(16) float ksm[2 * 144 * 20];
    __shared__ __align__(16) float vsm[2 * 144 * 20];
    __shared__ __align__(16) float rhs_[23 * 16];
    __shared__ __align__(16) float rws_[23 * 16];

    const int hp  = blockIdx.x % 3;
    const int win = blockIdx.x / 3;
    const int b   = win >> 10;
    const int wy  = (win >> 5) & 31;
    const int wx  = win & 31;
    const int tid = threadIdx.x;
    const int h0  = hp * 2;

    for (int i = tid; i < 23 * 16; i += 128) {
        rhs_[i] = rel_h[i];
        rws_[i] = rel_w[i];
    }

    const int y0 = wy * 8 - 2, x0 = wx * 8 - 2;
    for (int i = tid; i < 2 * 16 * 144; i += 128) {
        int j  = i % 12;
        int tt = i / 12;
        int ii = tt % 12;  tt /= 12;
        int d  = tt & 15;
        int hh = tt >> 4;
        int gy = y0 + ii, gx = x0 + j;
        float kv = 0.f, vv = 0.f;
        if ((unsigned)gy < 256u && (unsigned)gx < 256u) {
            const float* p = g_qkv +
                ((size_t)b * 288 + 96 + (h0 + hh) * 16 + d) * HW + gy * IMGW + gx;
            kv = p[0];
            vv = p[(size_t)96 * HW];
        }
        int si = (hh * 144 + ii * 12 + j) * 20 + d;
        ksm[si] = kv;
        vsm[si] = vv;
    }
    __syncthreads();

    const int hh   = tid >> 6;
    const int head = h0 + hh;
    const int qi   = tid & 63;
    const int x    = qi >> 3, y = qi & 7;
    const int gy   = wy * 8 + x, gx = wx * 8 + y;

    ull qp[8];
    {
        const float* qb = g_qkv + ((size_t)b * 288 + head * 16) * HW + gy * IMGW + gx;
#pragma unroll
        for (int d = 0; d < 8; d++) {
            float a = SCALE * qb[(size_t)(2 * d) * HW];
            float c = SCALE * qb[(size_t)(2 * d + 1) * HW];
            qp[d] = pack2(a, c);
        }
    }

    float Bv[12];
#pragma unroll
    for (int kj = 0; kj < 12; kj++) {
        const ull* rw = (const ull*)&rws_[(kj - y + 11) * 16];
        ull s0 = 0, s1 = 0;
#pragma unroll
        for (int d = 0; d < 8; d += 2) {
            s0 = ffma2(qp[d],     rw[d],     s0);
            s1 = ffma2(qp[d + 1], rw[d + 1], s1);
        }
        float2 f = unpack2(fadd2(s0, s1));
        Bv[kj] = f.x + f.y;
    }

    float sden0 = 0.f, sden1 = 0.f, sden2 = 0.f, sden3 = 0.f;
    ull acc[8] = {};
    const unsigned kaddr = (unsigned)__cvta_generic_to_shared(&ksm[hh * 144 * 20]);
    const unsigned vaddr = (unsigned)__cvta_generic_to_shared(&vsm[hh * 144 * 20]);

    for (int ki = 0; ki < 12; ki++) {
        float aki;
        {
            const ull* rh = (const ull*)&rhs_[(ki - x + 11) * 16];
            ull s0 = 0, s1 = 0;
#pragma unroll
            for (int d = 0; d < 8; d += 2) {
                s0 = ffma2(qp[d],     rh[d],     s0);
                s1 = ffma2(qp[d + 1], rh[d + 1], s1);
            }
            float2 f = unpack2(fadd2(s0, s1));
            aki = f.x + f.y;
        }

        const unsigned kro = kaddr + ki * 12 * 80;
        const unsigned vro = vaddr + ki * 12 * 80;

        float l[12];
#pragma unroll
        for (int kj = 0; kj < 12; kj++) {
            ull k0, k1, k2, k3, k4, k5, k6, k7;
            lds2x64(k0, k1, kro + kj * 80);
            lds2x64(k2, k3, kro + kj * 80 + 16);
            lds2x64(k4, k5, kro + kj * 80 + 32);
            lds2x64(k6, k7, kro + kj * 80 + 48);
            ull la = pack2(aki, Bv[kj]);
            la = ffma2(qp[0], k0, la);
            la = ffma2(qp[1], k1, la);
            la = ffma2(qp[2], k2, la);
            la = ffma2(qp[3], k3, la);
            la = ffma2(qp[4], k4, la);
            la = ffma2(qp[5], k5, la);
            la = ffma2(qp[6], k6, la);
            la = ffma2(qp[7], k7, la);
            float2 lf = unpack2(la);
            l[kj] = lf.x + lf.y;
        }

        float p[12];
#pragma unroll
        for (int kj = 0; kj < 12; kj++)
            p[kj] = __expf(l[kj]);
        sden0 += p[0] + p[4];
        sden1 += p[1] + p[5];
        sden2 += p[2] + p[6];
        sden3 += p[3] + p[7];
        sden0 += p[8];
        sden1 += p[9];
        sden2 += p[10];
        sden3 += p[11];

#pragma unroll
        for (int kj = 0; kj < 12; kj++) {
            ull pd = pack2(p[kj], p[kj]);
            ull v0, v1, v2, v3, v4, v5, v6, v7;
            lds2x64(v0, v1, vro + kj * 80);
            lds2x64(v2, v3, vro + kj * 80 + 16);
            lds2x64(v4, v5, vro + kj * 80 + 32);
            lds2x64(v6, v7, vro + kj * 80 + 48);
            acc[0] = ffma2(pd, v0, acc[0]);
            acc[1] = ffma2(pd, v1, acc[1]);
            acc[2] = ffma2(pd, v2, acc[2]);
            acc[3] = ffma2(pd, v3, acc[3]);
            acc[4] = ffma2(pd, v4, acc[4]);
            acc[5] = ffma2(pd, v5, acc[5]);
            acc[6] = ffma2(pd, v6, acc[6]);
            acc[7] = ffma2(pd, v7, acc[7]);
        }
    }

    float inv = 1.f / ((sden0 + sden1) + (sden2 + sden3));
    float* outp = g_att + ((size_t)b * 96 + head * 16) * HW + gy * IMGW + gx;
#pragma unroll
    for (int j = 0; j < 8; j++) {
        float2 f = unpack2(acc[j]);
        outp[(size_t)(2 * j) * HW]     = f.x * inv;
        outp[(size_t)(2 * j + 1) * HW] = f.y * inv;
    }
}

// ---------------------------------------------------------------------------
extern "C" void kernel_launch(void* const* d_in, const int* in_sizes, int n_in,
                              void* d_out, int out_size)
{
    (void)in_sizes; (void)n_in; (void)out_size;
    const float* x      = (const float*)d_in[0];
    const float* qkv_w  = (const float*)d_in[1];
    const float* qkv_b  = (const float*)d_in[2];
    const float* proj_w = (const float*)d_in[3];
    const float* proj_b = (const float*)d_in[4];
    const float* rel_h  = (const float*)d_in[5];
    const float* rel_w  = (const float*)d_in[6];
    float* out = (float*)d_out;

    float* qkv_ptr = nullptr;
    float* att_ptr = nullptr;
    cudaGetSymbolAddress((void**)&qkv_ptr, g_qkv);
    cudaGetSymbolAddress((void**)&att_ptr, g_att);

    // 1) QKV pointwise GEMM (tensor cores, 2-pass tf32, pipelined)
    mma_gemm<288><<<dim3(HW / 256, 288 / 32, 2), 256>>>(x, qkv_w, qkv_b, qkv_ptr);

    // 2) Windowed halo attention with rel-pos + softmax
    attn_kernel<<<2 * NWIN * NWIN * 3, 128>>>(rel_h, rel_w);

    // 3) Output projection (tensor cores, 2-pass tf32, pipelined)
    mma_gemm<96><<<dim3(HW / 256, 96 / 32, 2), 256>>>(att_ptr, proj_w, proj_b, out);
}